// round 6
// baseline (speedup 1.0000x reference)
#include <cuda_runtime.h>
#include <cuda_bf16.h>
#include <stdint.h>

#define N_NODES  1000000
#define N_EDGES  16000000
#define N_GRAPHS 10000

// Scratch: node features x and accumulator (x + sum of neighbor x).
__device__ float4 g_x[N_NODES * 2];
__device__ float4 g_acc[N_NODES * 2];

// ---------------------------------------------------------------------------
// Kernel 0: out[g] = fcb[0]  (d_out poisoned before timing)
// ---------------------------------------------------------------------------
__global__ void k_init_out(float* __restrict__ out, const float* __restrict__ fcb) {
    int i = blockIdx.x * blockDim.x + threadIdx.x;
    if (i < N_GRAPHS) out[i] = fcb[0];
}

// ---------------------------------------------------------------------------
// Kernel 1: build x = [pos | emb[z]] and initialize acc = x
// ---------------------------------------------------------------------------
__global__ void k_build_x(const float* __restrict__ pos,
                          const int*   __restrict__ z,
                          const float* __restrict__ emb) {
    int i = blockIdx.x * blockDim.x + threadIdx.x;
    if (i >= N_NODES) return;
    int zi = z[i];
    const float* e = emb + zi * 5;
    float4 lo = make_float4(pos[3 * i + 0], pos[3 * i + 1], pos[3 * i + 2], e[0]);
    float4 hi = make_float4(e[1], e[2], e[3], e[4]);
    g_x[2 * i + 0]   = lo;
    g_x[2 * i + 1]   = hi;
    g_acc[2 * i + 0] = lo;
    g_acc[2 * i + 1] = hi;
}

// ---------------------------------------------------------------------------
// Kernel 2: edge scatter-add.  acc[dst] += x[src]  (8 floats / edge)
// ---------------------------------------------------------------------------
__global__ void k_edges(const int* __restrict__ ei) {
    int e = blockIdx.x * blockDim.x + threadIdx.x;
    if (e >= N_EDGES) return;
    int s = __ldcs(&ei[e]);
    int d = __ldcs(&ei[N_EDGES + e]);
    float4 lo = __ldg(&g_x[2 * s + 0]);
    float4 hi = __ldg(&g_x[2 * s + 1]);
    float4* p = &g_acc[2 * d];
    asm volatile("red.global.add.v4.f32 [%0], {%1,%2,%3,%4};"
                 :: "l"(p), "f"(lo.x), "f"(lo.y), "f"(lo.z), "f"(lo.w) : "memory");
    asm volatile("red.global.add.v4.f32 [%0], {%1,%2,%3,%4};"
                 :: "l"(p + 1), "f"(hi.x), "f"(hi.y), "f"(hi.z), "f"(hi.w) : "memory");
}

// ---------------------------------------------------------------------------
// Kernel 3 (v3): register-blocked packed-f32x2 GEMM for layer 2.
// CTA = 128 nodes, 128 threads.
//   Stage A: layer1 (fp32, per-thread node) -> h1 packed as node-pairs in smem
//            h1p[k][pair] : u64 = (h1[node2p][k], h1[node2p+1][k])
//            W2 in smem duplicated: w2p[k][j] : u64 = (W2[k][j], W2[k][j])
//   Stage B: thread (jg,ng) owns 4 node-pairs x 8 outcols -> 32 f32x2 accs.
//            per k: 2+4 LDS.128 feed 32 FFMA2 (weights/h broadcast in warp).
//   Stage C: relu + fcW dot per node partials -> smem -> per-node sum ->
//            warp-segmented atomicAdd by batch (sorted).
// dynamic smem: [0,32K) w2p, [32K,64K) h1p; partials reuse w2p after sync.
// ---------------------------------------------------------------------------
#define OFF_W2P 0
#define OFF_H1P 32768
#define DSM_BYTES 65536

__global__ void __launch_bounds__(128)
k_mlp(const float* __restrict__ W1, const float* __restrict__ b1,
      const float* __restrict__ W2, const float* __restrict__ b2,
      const float* __restrict__ fcW,
      const int*   __restrict__ batch,
      float* __restrict__ out) {
    extern __shared__ char dsm[];
    uint32_t dsm_s = (uint32_t)__cvta_generic_to_shared(dsm);

    __shared__ float sW1[8 * 64];
    __shared__ float sb1[64], sb2[64], sfc[64];

    int t = threadIdx.x;
    int lane = t & 31;

    for (int k = t; k < 8 * 64; k += 128) sW1[k] = W1[k];
    if (t < 64) { sb1[t] = b1[t]; sb2[t] = b2[t]; sfc[t] = fcW[t]; }

    // W2 -> duplicated pairs w2p[k][j] = (w,w); row stride 512B
    for (int idx = t; idx < 4096; idx += 128) {
        float w = __ldg(&W2[idx]);                 // idx = k*64 + j
        asm volatile("st.shared.v2.f32 [%0], {%1,%1};"
                     :: "r"(dsm_s + OFF_W2P + idx * 8), "f"(w));
    }
    __syncthreads();   // sW1/sb1 ready for layer 1

    // ---- Stage A: layer 1 for node i = blockBase + t ----
    int i = blockIdx.x * 128 + t;
    int g = -1;
    float in8[8] = {0, 0, 0, 0, 0, 0, 0, 0};
    if (i < N_NODES) {
        g = batch[i];
        float4 lo = g_acc[2 * i + 0];
        float4 hi = g_acc[2 * i + 1];
        in8[0] = lo.x; in8[1] = lo.y; in8[2] = lo.z; in8[3] = lo.w;
        in8[4] = hi.x; in8[5] = hi.y; in8[6] = hi.z; in8[7] = hi.w;
    }
    #pragma unroll
    for (int c = 0; c < 4; c++) {
        float a0[16];
        #pragma unroll
        for (int j = 0; j < 16; j++) a0[j] = sb1[c * 16 + j];
        #pragma unroll
        for (int k = 0; k < 8; k++) {
            const float4* w4 = (const float4*)(sW1 + k * 64 + c * 16);
            float ik = in8[k];
            #pragma unroll
            for (int j4 = 0; j4 < 4; j4++) {
                float4 w = w4[j4];
                a0[j4 * 4 + 0] += ik * w.x;
                a0[j4 * 4 + 1] += ik * w.y;
                a0[j4 * 4 + 2] += ik * w.z;
                a0[j4 * 4 + 3] += ik * w.w;
            }
        }
        // h1p[k][pair]: scalar store at k*512 + t*4 (consecutive t -> no conflicts)
        #pragma unroll
        for (int j = 0; j < 16; j++) {
            float v = fmaxf(a0[j], 0.0f);
            asm volatile("st.shared.f32 [%0], %1;"
                         :: "r"(dsm_s + OFF_H1P + (c * 16 + j) * 512 + t * 4), "f"(v));
        }
    }
    __syncthreads();   // h1p + w2p ready

    // ---- Stage B: layer 2 GEMM tile ----
    // t = jg*16 + ng : jg in [0,8) -> outcols jg*8..+7 ; ng in [0,16) -> nodes ng*8..+7
    int jg = t >> 4;
    int ng = t & 15;
    uint32_t h_base = dsm_s + OFF_H1P + ng * 32;   // 4 pairs = 32B
    uint32_t w_base = dsm_s + OFF_W2P + jg * 64;   // 8 dup-pairs = 64B

    unsigned long long acc[4][8];
    #pragma unroll
    for (int j = 0; j < 8; j++) {
        float b = sb2[jg * 8 + j];
        unsigned long long bb;
        asm("mov.b64 %0, {%1,%1};" : "=l"(bb) : "f"(b));
        #pragma unroll
        for (int p = 0; p < 4; p++) acc[p][j] = bb;
    }

    #pragma unroll 4
    for (int k = 0; k < 64; k++) {
        unsigned long long H[4], W[8];
        asm volatile("ld.shared.v2.u64 {%0,%1}, [%2];"
                     : "=l"(H[0]), "=l"(H[1]) : "r"(h_base + k * 512));
        asm volatile("ld.shared.v2.u64 {%0,%1}, [%2];"
                     : "=l"(H[2]), "=l"(H[3]) : "r"(h_base + k * 512 + 16));
        asm volatile("ld.shared.v2.u64 {%0,%1}, [%2];"
                     : "=l"(W[0]), "=l"(W[1]) : "r"(w_base + k * 512));
        asm volatile("ld.shared.v2.u64 {%0,%1}, [%2];"
                     : "=l"(W[2]), "=l"(W[3]) : "r"(w_base + k * 512 + 16));
        asm volatile("ld.shared.v2.u64 {%0,%1}, [%2];"
                     : "=l"(W[4]), "=l"(W[5]) : "r"(w_base + k * 512 + 32));
        asm volatile("ld.shared.v2.u64 {%0,%1}, [%2];"
                     : "=l"(W[6]), "=l"(W[7]) : "r"(w_base + k * 512 + 48));
        #pragma unroll
        for (int p = 0; p < 4; p++)
            #pragma unroll
            for (int j = 0; j < 8; j++)
                asm("fma.rn.f32x2 %0, %1, %2, %0;"
                    : "+l"(acc[p][j]) : "l"(H[p]), "l"(W[j]));
    }

    // ---- Stage C: relu + fcW partial dot, per (node, jg) ----
    __syncthreads();   // everyone done reading w2p; reuse as partial buffer
    #pragma unroll
    for (int p = 0; p < 4; p++) {
        float slo = 0.0f, shi = 0.0f;
        #pragma unroll
        for (int j = 0; j < 8; j++) {
            float f = sfc[jg * 8 + j];
            float lo, hi;
            asm("mov.b64 {%0,%1}, %2;" : "=f"(lo), "=f"(hi) : "l"(acc[p][j]));
            slo += fmaxf(lo, 0.0f) * f;
            shi += fmaxf(hi, 0.0f) * f;
        }
        int n0 = ng * 8 + 2 * p;            // local node of .lo
        // partial[node][jg] at node*32 + jg*4 (4KB inside old w2p region)
        asm volatile("st.shared.f32 [%0], %1;"
                     :: "r"(dsm_s + OFF_W2P + n0 * 32 + jg * 4), "f"(slo));
        asm volatile("st.shared.f32 [%0], %1;"
                     :: "r"(dsm_s + OFF_W2P + (n0 + 1) * 32 + jg * 4), "f"(shi));
    }
    __syncthreads();

    // per-node sum of 8 partials (thread t <-> node t), then segment-atomic
    float s = 0.0f;
    {
        float4 q0, q1;
        asm volatile("ld.shared.v4.f32 {%0,%1,%2,%3}, [%4];"
                     : "=f"(q0.x), "=f"(q0.y), "=f"(q0.z), "=f"(q0.w)
                     : "r"(dsm_s + OFF_W2P + t * 32));
        asm volatile("ld.shared.v4.f32 {%0,%1,%2,%3}, [%4];"
                     : "=f"(q1.x), "=f"(q1.y), "=f"(q1.z), "=f"(q1.w)
                     : "r"(dsm_s + OFF_W2P + t * 32 + 16));
        s = ((q0.x + q0.y) + (q0.z + q0.w)) + ((q1.x + q1.y) + (q1.z + q1.w));
    }

    const unsigned full = 0xffffffffu;
    #pragma unroll
    for (int d = 1; d < 32; d <<= 1) {
        float v  = __shfl_down_sync(full, s, d);
        int   go = __shfl_down_sync(full, g, d);
        if (lane + d < 32 && go == g) s += v;
    }
    int gup = __shfl_up_sync(full, g, 1);
    if (g >= 0 && (lane == 0 || gup != g))
        atomicAdd(&out[g], s);
}

// ---------------------------------------------------------------------------
// launch
// ---------------------------------------------------------------------------
extern "C" void kernel_launch(void* const* d_in, const int* in_sizes, int n_in,
                              void* d_out, int out_size) {
    const float* pos   = (const float*)d_in[0];
    const int*   z     = (const int*)  d_in[1];
    const int*   ei    = (const int*)  d_in[2];
    const int*   batch = (const int*)  d_in[3];
    const float* emb   = (const float*)d_in[4];
    const float* W1    = (const float*)d_in[5];
    const float* b1    = (const float*)d_in[6];
    const float* W2    = (const float*)d_in[7];
    const float* b2    = (const float*)d_in[8];
    const float* fcW   = (const float*)d_in[9];
    const float* fcb   = (const float*)d_in[10];
    float* out = (float*)d_out;

    static int smem_set = 0;
    if (!smem_set) {
        cudaFuncSetAttribute(k_mlp, cudaFuncAttributeMaxDynamicSharedMemorySize, DSM_BYTES);
        smem_set = 1;
    }

    k_init_out<<<(N_GRAPHS + 255) / 256, 256>>>(out, fcb);
    k_build_x<<<(N_NODES + 255) / 256, 256>>>(pos, z, emb);
    k_edges<<<(N_EDGES + 255) / 256, 256>>>(ei);
    k_mlp<<<(N_NODES + 127) / 128, 128, DSM_BYTES>>>(W1, b1, W2, b2, fcW, batch, out);
}